// round 1
// baseline (speedup 1.0000x reference)
#include <cuda_runtime.h>

#define DIMD  1024
#define NH    16
#define DH    64
#define BATCH 4
#define SEQ   2048
#define MTOT  (BATCH*SEQ)   // 8192

// Scratch (allocation-free rule: __device__ globals)
__device__ float g_Q[BATCH*NH*SEQ*DH];   // 32 MB, [B,H,S,Dh]
__device__ float g_K[BATCH*NH*SEQ*DH];
__device__ float g_V[BATCH*NH*SEQ*DH];
__device__ float g_A[MTOT*DIMD];         // attention output, [B,S,D]

// ---------------------------------------------------------------------------
// 128x128x8 SGEMM, 256 threads, 8x8 register tile. K fixed at 1024.
// MODE 0: C = x @ w_qkv + b, scatter into g_Q/g_K/g_V as [B,H,S,Dh]
// MODE 1: C = g_A @ w_proj + b, plain row-major write to out
// ---------------------------------------------------------------------------
template<int MODE>
__global__ __launch_bounds__(256)
void gemm128(const float* __restrict__ A, const float* __restrict__ B,
             const float* __restrict__ bias, float* __restrict__ out, int N)
{
    const int K = DIMD;
    __shared__ float As[8][128];   // transposed: As[k][m]
    __shared__ float Bs[8][128];   // Bs[k][n]

    const int tid = threadIdx.x;
    const int rowStart = blockIdx.y * 128;
    const int colStart = blockIdx.x * 128;

    const int aRow = tid >> 1;            // 0..127
    const int aCol = (tid & 1) << 2;      // 0 or 4
    const int bRow = tid >> 5;            // 0..7
    const int bCol = (tid & 31) << 2;     // 0..124
    const int ty = tid >> 4;              // 0..15
    const int tx = tid & 15;              // 0..15

    const float* Ap = (MODE == 0) ? A : g_A;

    float acc[8][8];
    #pragma unroll
    for (int i = 0; i < 8; i++)
        #pragma unroll
        for (int j = 0; j < 8; j++) acc[i][j] = 0.f;

    for (int k0 = 0; k0 < K; k0 += 8) {
        float4 av = *(const float4*)(Ap + (long)(rowStart + aRow)*K + k0 + aCol);
        As[aCol+0][aRow] = av.x;
        As[aCol+1][aRow] = av.y;
        As[aCol+2][aRow] = av.z;
        As[aCol+3][aRow] = av.w;
        *(float4*)(&Bs[bRow][bCol]) =
            *(const float4*)(B + (long)(k0 + bRow)*N + colStart + bCol);
        __syncthreads();

        #pragma unroll
        for (int kk = 0; kk < 8; kk++) {
            float a[8], b[8];
            *(float4*)(a)   = *(const float4*)(&As[kk][ty*8]);
            *(float4*)(a+4) = *(const float4*)(&As[kk][ty*8+4]);
            *(float4*)(b)   = *(const float4*)(&Bs[kk][tx*8]);
            *(float4*)(b+4) = *(const float4*)(&Bs[kk][tx*8+4]);
            #pragma unroll
            for (int i = 0; i < 8; i++)
                #pragma unroll
                for (int j = 0; j < 8; j++)
                    acc[i][j] += a[i] * b[j];
        }
        __syncthreads();
    }

    if (MODE == 0) {
        // scatter into Q/K/V with [B,H,S,Dh] layout
        #pragma unroll
        for (int i = 0; i < 8; i++) {
            const int m  = rowStart + ty*8 + i;
            const int bb = m >> 11;        // / SEQ
            const int s  = m & 2047;
            #pragma unroll
            for (int jv = 0; jv < 2; jv++) {
                const int n = colStart + tx*8 + jv*4;
                float4 v;
                v.x = acc[i][jv*4+0] + bias[n+0];
                v.y = acc[i][jv*4+1] + bias[n+1];
                v.z = acc[i][jv*4+2] + bias[n+2];
                v.w = acc[i][jv*4+3] + bias[n+3];
                const int part = n >> 10;         // 0=q 1=k 2=v (uniform per block)
                const int dcol = n & 1023;
                const int head = dcol >> 6;
                const int dh   = dcol & 63;
                float* dst = (part == 0) ? g_Q : (part == 1) ? g_K : g_V;
                const int idx = (((bb*NH + head)*SEQ + s) << 6) + dh;
                *(float4*)(dst + idx) = v;
            }
        }
    } else {
        #pragma unroll
        for (int i = 0; i < 8; i++) {
            const int m = rowStart + ty*8 + i;
            #pragma unroll
            for (int jv = 0; jv < 2; jv++) {
                const int n = colStart + tx*8 + jv*4;
                float4 v;
                v.x = acc[i][jv*4+0] + bias[n+0];
                v.y = acc[i][jv*4+1] + bias[n+1];
                v.z = acc[i][jv*4+2] + bias[n+2];
                v.w = acc[i][jv*4+3] + bias[n+3];
                *(float4*)(out + (long)m*N + n) = v;
            }
        }
    }
}

// ---------------------------------------------------------------------------
// Flash attention, fp32. One block = (b, h, 64-query tile). 256 threads as
// 16x16; each thread owns a 4x4 micro-tile. K stored transposed in SMEM
// (conflict-free column access); the K buffer is reused for P. 48 KB static.
// ---------------------------------------------------------------------------
__global__ __launch_bounds__(256)
void attn_kernel()
{
    __shared__ float Qs[64][64];
    __shared__ float KP[64][64];   // phase 1: K^T  (KP[d][krow]); phase 2: P (KP[q][k])
    __shared__ float Vs[64][64];

    const int tid = threadIdx.x;
    const int ty = tid >> 4, tx = tid & 15;
    const int qt = blockIdx.x;
    const int h  = blockIdx.y;
    const int b  = blockIdx.z;
    const int q0 = qt << 6;

    const long headBase = (long)(b*NH + h) * SEQ * DH;
    const float* Qg = g_Q + headBase;
    const float* Kg = g_K + headBase;
    const float* Vg = g_V + headBase;

    // Load Q tile, pre-scaled by 1/sqrt(Dh) = 0.125
    {
        const int r  = tid >> 2;
        const int d0 = (tid & 3) << 4;
        #pragma unroll
        for (int v = 0; v < 4; v++) {
            float4 t = *(const float4*)(Qg + (q0 + r)*DH + d0 + v*4);
            t.x *= 0.125f; t.y *= 0.125f; t.z *= 0.125f; t.w *= 0.125f;
            *(float4*)(&Qs[r][d0 + v*4]) = t;
        }
    }

    float m_run[4], l_run[4], o[4][4];
    #pragma unroll
    for (int i = 0; i < 4; i++) {
        m_run[i] = -1e30f; l_run[i] = 0.f;
        #pragma unroll
        for (int j = 0; j < 4; j++) o[i][j] = 0.f;
    }

    for (int kt = 0; kt <= qt; kt++) {
        const int k0 = kt << 6;
        __syncthreads();   // Q visible (iter 0) / prior PV reads done

        // Load K (transposed into KP) and V
        {
            const int r  = tid >> 2;
            const int d0 = (tid & 3) << 4;
            #pragma unroll
            for (int v = 0; v < 4; v++) {
                float4 t = *(const float4*)(Kg + (k0 + r)*DH + d0 + v*4);
                KP[d0 + v*4 + 0][r] = t.x;
                KP[d0 + v*4 + 1][r] = t.y;
                KP[d0 + v*4 + 2][r] = t.z;
                KP[d0 + v*4 + 3][r] = t.w;
                *(float4*)(&Vs[r][d0 + v*4]) =
                    *(const float4*)(Vg + (k0 + r)*DH + d0 + v*4);
            }
        }
        __syncthreads();

        // S = Q K^T (scale folded into Q)
        float s[4][4];
        #pragma unroll
        for (int i = 0; i < 4; i++)
            #pragma unroll
            for (int j = 0; j < 4; j++) s[i][j] = 0.f;

        #pragma unroll 4
        for (int d = 0; d < 64; d += 4) {
            float4 q[4], k[4];
            #pragma unroll
            for (int i = 0; i < 4; i++) q[i] = *(const float4*)(&Qs[ty*4+i][d]);
            #pragma unroll
            for (int u = 0; u < 4; u++) k[u] = *(const float4*)(&KP[d+u][tx*4]);
            #pragma unroll
            for (int i = 0; i < 4; i++) {
                s[i][0] += q[i].x*k[0].x + q[i].y*k[1].x + q[i].z*k[2].x + q[i].w*k[3].x;
                s[i][1] += q[i].x*k[0].y + q[i].y*k[1].y + q[i].z*k[2].y + q[i].w*k[3].y;
                s[i][2] += q[i].x*k[0].z + q[i].y*k[1].z + q[i].z*k[2].z + q[i].w*k[3].z;
                s[i][3] += q[i].x*k[0].w + q[i].y*k[1].w + q[i].z*k[2].w + q[i].w*k[3].w;
            }
        }

        // Causal mask: only the diagonal tile needs it (q0 == k0 there)
        if (kt == qt) {
            #pragma unroll
            for (int i = 0; i < 4; i++)
                #pragma unroll
                for (int j = 0; j < 4; j++)
                    if (tx*4 + j > ty*4 + i) s[i][j] = -1e30f;
        }

        // Online softmax update (row stats across the 16 tx lanes)
        #pragma unroll
        for (int i = 0; i < 4; i++) {
            float mx = fmaxf(fmaxf(s[i][0], s[i][1]), fmaxf(s[i][2], s[i][3]));
            mx = fmaxf(mx, __shfl_xor_sync(0xffffffffu, mx, 1));
            mx = fmaxf(mx, __shfl_xor_sync(0xffffffffu, mx, 2));
            mx = fmaxf(mx, __shfl_xor_sync(0xffffffffu, mx, 4));
            mx = fmaxf(mx, __shfl_xor_sync(0xffffffffu, mx, 8));
            const float m_new = fmaxf(m_run[i], mx);
            const float alpha = __expf(m_run[i] - m_new);
            m_run[i] = m_new;
            float ps = 0.f;
            #pragma unroll
            for (int j = 0; j < 4; j++) {
                s[i][j] = __expf(s[i][j] - m_new);
                ps += s[i][j];
            }
            ps += __shfl_xor_sync(0xffffffffu, ps, 1);
            ps += __shfl_xor_sync(0xffffffffu, ps, 2);
            ps += __shfl_xor_sync(0xffffffffu, ps, 4);
            ps += __shfl_xor_sync(0xffffffffu, ps, 8);
            l_run[i] = l_run[i]*alpha + ps;
            #pragma unroll
            for (int j = 0; j < 4; j++) o[i][j] *= alpha;
        }

        __syncthreads();   // all lanes done reading KP as K^T
        #pragma unroll
        for (int i = 0; i < 4; i++)
            *(float4*)(&KP[ty*4+i][tx*4]) =
                make_float4(s[i][0], s[i][1], s[i][2], s[i][3]);
        __syncthreads();

        // O += P @ V
        #pragma unroll 8
        for (int kk = 0; kk < 64; kk++) {
            const float4 vv = *(const float4*)(&Vs[kk][tx*4]);
            const float p0 = KP[ty*4+0][kk];
            const float p1 = KP[ty*4+1][kk];
            const float p2 = KP[ty*4+2][kk];
            const float p3 = KP[ty*4+3][kk];
            o[0][0] += p0*vv.x; o[0][1] += p0*vv.y; o[0][2] += p0*vv.z; o[0][3] += p0*vv.w;
            o[1][0] += p1*vv.x; o[1][1] += p1*vv.y; o[1][2] += p1*vv.z; o[1][3] += p1*vv.w;
            o[2][0] += p2*vv.x; o[2][1] += p2*vv.y; o[2][2] += p2*vv.z; o[2][3] += p2*vv.w;
            o[3][0] += p3*vv.x; o[3][1] += p3*vv.y; o[3][2] += p3*vv.z; o[3][3] += p3*vv.w;
        }
    }

    // Normalize and write merged-head layout [B,S,D]
    const long outBase = (long)(b*SEQ + q0) * DIMD + h*DH;
    #pragma unroll
    for (int i = 0; i < 4; i++) {
        const float inv = 1.0f / l_run[i];
        float4 v = make_float4(o[i][0]*inv, o[i][1]*inv, o[i][2]*inv, o[i][3]*inv);
        *(float4*)(g_A + outBase + (long)(ty*4 + i)*DIMD + tx*4) = v;
    }
}

// ---------------------------------------------------------------------------
extern "C" void kernel_launch(void* const* d_in, const int* in_sizes, int n_in,
                              void* d_out, int out_size)
{
    const float* x      = (const float*)d_in[0];
    const float* w_qkv  = (const float*)d_in[1];
    const float* b_qkv  = (const float*)d_in[2];
    const float* w_proj = (const float*)d_in[3];
    const float* b_proj = (const float*)d_in[4];
    float* out = (float*)d_out;

    // QKV projection: [8192,1024] @ [1024,3072] -> scatter to g_Q/g_K/g_V
    gemm128<0><<<dim3(3*DIMD/128, MTOT/128), 256>>>(x, w_qkv, b_qkv, nullptr, 3*DIMD);
    // Causal flash attention per (b, h, 64-row q-tile)
    attn_kernel<<<dim3(SEQ/64, NH, BATCH), 256>>>();
    // Output projection: g_A @ [1024,1024] -> out
    gemm128<1><<<dim3(DIMD/128, MTOT/128), 256>>>(nullptr, w_proj, b_proj, out, DIMD);
}

// round 2
// speedup vs baseline: 1.5904x; 1.5904x over previous
#include <cuda_runtime.h>

#define DIMD  1024
#define NH    16
#define DH    64
#define BATCH 4
#define SEQ   2048
#define MTOT  (BATCH*SEQ)   // 8192

// Scratch (allocation-free rule: __device__ globals)
__device__ float g_Q[BATCH*NH*SEQ*DH];   // [B,H,S,Dh]
__device__ float g_K[BATCH*NH*SEQ*DH];
__device__ float g_V[BATCH*NH*SEQ*DH];
__device__ float g_A[MTOT*DIMD];         // attention output, [B,S,D]

__device__ __forceinline__ float f2tf32(float x) {
    unsigned u;
    asm("cvt.rna.tf32.f32 %0, %1;" : "=r"(u) : "f"(x));
    return __uint_as_float(u);
}

__device__ __forceinline__ void mma_tf32(
    float& c0, float& c1, float& c2, float& c3,
    unsigned a0, unsigned a1, unsigned a2, unsigned a3,
    unsigned b0, unsigned b1)
{
    asm volatile(
        "mma.sync.aligned.m16n8k8.row.col.f32.tf32.tf32.f32 "
        "{%0,%1,%2,%3}, {%4,%5,%6,%7}, {%8,%9}, {%0,%1,%2,%3};"
        : "+f"(c0), "+f"(c1), "+f"(c2), "+f"(c3)
        : "r"(a0), "r"(a1), "r"(a2), "r"(a3), "r"(b0), "r"(b1));
}

// ---------------------------------------------------------------------------
// TF32 tensor-core GEMM: C[M,N] = A[M,1024] @ B[1024,N] + bias
// Block tile 128x128, 256 threads = 8 warps (4 M x 2 N), warp tile 32x64.
// MODE 0: A = x, scatter C into g_Q/g_K/g_V as [B,H,S,Dh]
// MODE 1: A = g_A, plain row-major write to out
// ---------------------------------------------------------------------------
template<int MODE>
__global__ __launch_bounds__(256, 2)
void gemm_tf32(const float* __restrict__ A, const float* __restrict__ B,
               const float* __restrict__ bias, float* __restrict__ out, int N)
{
    const int K = DIMD;
    __shared__ float As[128][36];   // [m][k], stride 36 -> conflict-free frags
    __shared__ float Bs[32][136];   // [k][n], stride 136 -> conflict-free frags

    const int tid  = threadIdx.x;
    const int lane = tid & 31;
    const int warp = tid >> 5;
    const int warp_m = warp & 3;        // 0..3 -> 32-row strip
    const int warp_n = warp >> 2;       // 0..1 -> 64-col strip
    const int qr = lane >> 2;           // 0..7
    const int qc = lane & 3;            // 0..3

    const int rowStart = blockIdx.y * 128;
    const int colStart = blockIdx.x * 128;
    const float* Ap = (MODE == 0) ? A : g_A;

    float acc[2][8][4];
    #pragma unroll
    for (int i = 0; i < 2; i++)
        #pragma unroll
        for (int j = 0; j < 8; j++)
            #pragma unroll
            for (int c = 0; c < 4; c++) acc[i][j][c] = 0.f;

    for (int k0 = 0; k0 < K; k0 += 32) {
        // stage global loads in registers before the barrier
        float4 av[4], bv[4];
        #pragma unroll
        for (int i = 0; i < 4; i++) {
            const int q = tid + i*256;
            const int ar = q >> 3, akq = q & 7;            // A: 128 rows x 8 quads
            av[i] = *(const float4*)(Ap + (long)(rowStart + ar)*K + k0 + akq*4);
            const int br = q >> 5, bnq = q & 31;           // B: 32 rows x 32 quads
            bv[i] = *(const float4*)(B + (long)(k0 + br)*N + colStart + bnq*4);
        }
        __syncthreads();   // previous stage's compute done
        #pragma unroll
        for (int i = 0; i < 4; i++) {
            const int q = tid + i*256;
            const int ar = q >> 3, akq = q & 7;
            float* as = &As[ar][akq*4];
            as[0] = f2tf32(av[i].x); as[1] = f2tf32(av[i].y);
            as[2] = f2tf32(av[i].z); as[3] = f2tf32(av[i].w);
            const int br = q >> 5, bnq = q & 31;
            float* bs = &Bs[br][bnq*4];
            bs[0] = f2tf32(bv[i].x); bs[1] = f2tf32(bv[i].y);
            bs[2] = f2tf32(bv[i].z); bs[3] = f2tf32(bv[i].w);
        }
        __syncthreads();

        #pragma unroll
        for (int ks = 0; ks < 4; ks++) {
            const int kb = ks * 8;
            unsigned a[2][4], b[8][2];
            #pragma unroll
            for (int ma = 0; ma < 2; ma++) {
                const int r = warp_m*32 + ma*16 + qr;
                a[ma][0] = __float_as_uint(As[r    ][kb + qc    ]);
                a[ma][1] = __float_as_uint(As[r + 8][kb + qc    ]);
                a[ma][2] = __float_as_uint(As[r    ][kb + qc + 4]);
                a[ma][3] = __float_as_uint(As[r + 8][kb + qc + 4]);
            }
            #pragma unroll
            for (int nb = 0; nb < 8; nb++) {
                const int cc = warp_n*64 + nb*8 + qr;
                b[nb][0] = __float_as_uint(Bs[kb + qc    ][cc]);
                b[nb][1] = __float_as_uint(Bs[kb + qc + 4][cc]);
            }
            #pragma unroll
            for (int ma = 0; ma < 2; ma++)
                #pragma unroll
                for (int nb = 0; nb < 8; nb++)
                    mma_tf32(acc[ma][nb][0], acc[ma][nb][1],
                             acc[ma][nb][2], acc[ma][nb][3],
                             a[ma][0], a[ma][1], a[ma][2], a[ma][3],
                             b[nb][0], b[nb][1]);
        }
    }

    // Epilogue: c0,c1 -> (row, col + {0,1}); c2,c3 -> (row+8, ...)
    #pragma unroll
    for (int ma = 0; ma < 2; ma++) {
        const int row0 = rowStart + warp_m*32 + ma*16 + qr;
        #pragma unroll
        for (int nb = 0; nb < 8; nb++) {
            const int col = colStart + warp_n*64 + nb*8 + qc*2;
            const float b0 = bias[col], b1 = bias[col + 1];
            float2 v0 = make_float2(acc[ma][nb][0] + b0, acc[ma][nb][1] + b1);
            float2 v1 = make_float2(acc[ma][nb][2] + b0, acc[ma][nb][3] + b1);
            if (MODE == 0) {
                const int part = col >> 10;
                const int dcol = col & 1023;
                const int head = dcol >> 6;
                const int dh   = dcol & 63;
                float* dst = (part == 0) ? g_Q : (part == 1) ? g_K : g_V;
                {
                    const int bb = row0 >> 11, s = row0 & 2047;
                    *(float2*)(dst + (((bb*NH + head)*SEQ + s) << 6) + dh) = v0;
                }
                {
                    const int row1 = row0 + 8;
                    const int bb = row1 >> 11, s = row1 & 2047;
                    *(float2*)(dst + (((bb*NH + head)*SEQ + s) << 6) + dh) = v1;
                }
            } else {
                *(float2*)(out + (long)row0*N + col) = v0;
                *(float2*)(out + (long)(row0 + 8)*N + col) = v1;
            }
        }
    }
}

// ---------------------------------------------------------------------------
// Flash attention, fp32 (unchanged from round 1).
// ---------------------------------------------------------------------------
__global__ __launch_bounds__(256)
void attn_kernel()
{
    __shared__ float Qs[64][64];
    __shared__ float KP[64][64];
    __shared__ float Vs[64][64];

    const int tid = threadIdx.x;
    const int ty = tid >> 4, tx = tid & 15;
    const int qt = blockIdx.x;
    const int h  = blockIdx.y;
    const int b  = blockIdx.z;
    const int q0 = qt << 6;

    const long headBase = (long)(b*NH + h) * SEQ * DH;
    const float* Qg = g_Q + headBase;
    const float* Kg = g_K + headBase;
    const float* Vg = g_V + headBase;

    {
        const int r  = tid >> 2;
        const int d0 = (tid & 3) << 4;
        #pragma unroll
        for (int v = 0; v < 4; v++) {
            float4 t = *(const float4*)(Qg + (q0 + r)*DH + d0 + v*4);
            t.x *= 0.125f; t.y *= 0.125f; t.z *= 0.125f; t.w *= 0.125f;
            *(float4*)(&Qs[r][d0 + v*4]) = t;
        }
    }

    float m_run[4], l_run[4], o[4][4];
    #pragma unroll
    for (int i = 0; i < 4; i++) {
        m_run[i] = -1e30f; l_run[i] = 0.f;
        #pragma unroll
        for (int j = 0; j < 4; j++) o[i][j] = 0.f;
    }

    for (int kt = 0; kt <= qt; kt++) {
        const int k0 = kt << 6;
        __syncthreads();

        {
            const int r  = tid >> 2;
            const int d0 = (tid & 3) << 4;
            #pragma unroll
            for (int v = 0; v < 4; v++) {
                float4 t = *(const float4*)(Kg + (k0 + r)*DH + d0 + v*4);
                KP[d0 + v*4 + 0][r] = t.x;
                KP[d0 + v*4 + 1][r] = t.y;
                KP[d0 + v*4 + 2][r] = t.z;
                KP[d0 + v*4 + 3][r] = t.w;
                *(float4*)(&Vs[r][d0 + v*4]) =
                    *(const float4*)(Vg + (k0 + r)*DH + d0 + v*4);
            }
        }
        __syncthreads();

        float s[4][4];
        #pragma unroll
        for (int i = 0; i < 4; i++)
            #pragma unroll
            for (int j = 0; j < 4; j++) s[i][j] = 0.f;

        #pragma unroll 4
        for (int d = 0; d < 64; d += 4) {
            float4 q[4], k[4];
            #pragma unroll
            for (int i = 0; i < 4; i++) q[i] = *(const float4*)(&Qs[ty*4+i][d]);
            #pragma unroll
            for (int u = 0; u < 4; u++) k[u] = *(const float4*)(&KP[d+u][tx*4]);
            #pragma unroll
            for (int i = 0; i < 4; i++) {
                s[i][0] += q[i].x*k[0].x + q[i].y*k[1].x + q[i].z*k[2].x + q[i].w*k[3].x;
                s[i][1] += q[i].x*k[0].y + q[i].y*k[1].y + q[i].z*k[2].y + q[i].w*k[3].y;
                s[i][2] += q[i].x*k[0].z + q[i].y*k[1].z + q[i].z*k[2].z + q[i].w*k[3].z;
                s[i][3] += q[i].x*k[0].w + q[i].y*k[1].w + q[i].z*k[2].w + q[i].w*k[3].w;
            }
        }

        if (kt == qt) {
            #pragma unroll
            for (int i = 0; i < 4; i++)
                #pragma unroll
                for (int j = 0; j < 4; j++)
                    if (tx*4 + j > ty*4 + i) s[i][j] = -1e30f;
        }

        #pragma unroll
        for (int i = 0; i < 4; i++) {
            float mx = fmaxf(fmaxf(s[i][0], s[i][1]), fmaxf(s[i][2], s[i][3]));
            mx = fmaxf(mx, __shfl_xor_sync(0xffffffffu, mx, 1));
            mx = fmaxf(mx, __shfl_xor_sync(0xffffffffu, mx, 2));
            mx = fmaxf(mx, __shfl_xor_sync(0xffffffffu, mx, 4));
            mx = fmaxf(mx, __shfl_xor_sync(0xffffffffu, mx, 8));
            const float m_new = fmaxf(m_run[i], mx);
            const float alpha = __expf(m_run[i] - m_new);
            m_run[i] = m_new;
            float ps = 0.f;
            #pragma unroll
            for (int j = 0; j < 4; j++) {
                s[i][j] = __expf(s[i][j] - m_new);
                ps += s[i][j];
            }
            ps += __shfl_xor_sync(0xffffffffu, ps, 1);
            ps += __shfl_xor_sync(0xffffffffu, ps, 2);
            ps += __shfl_xor_sync(0xffffffffu, ps, 4);
            ps += __shfl_xor_sync(0xffffffffu, ps, 8);
            l_run[i] = l_run[i]*alpha + ps;
            #pragma unroll
            for (int j = 0; j < 4; j++) o[i][j] *= alpha;
        }

        __syncthreads();
        #pragma unroll
        for (int i = 0; i < 4; i++)
            *(float4*)(&KP[ty*4+i][tx*4]) =
                make_float4(s[i][0], s[i][1], s[i][2], s[i][3]);
        __syncthreads();

        #pragma unroll 8
        for (int kk = 0; kk < 64; kk++) {
            const float4 vv = *(const float4*)(&Vs[kk][tx*4]);
            const float p0 = KP[ty*4+0][kk];
            const float p1 = KP[ty*4+1][kk];
            const float p2 = KP[ty*4+2][kk];
            const float p3 = KP[ty*4+3][kk];
            o[0][0] += p0*vv.x; o[0][1] += p0*vv.y; o[0][2] += p0*vv.z; o[0][3] += p0*vv.w;
            o[1][0] += p1*vv.x; o[1][1] += p1*vv.y; o[1][2] += p1*vv.z; o[1][3] += p1*vv.w;
            o[2][0] += p2*vv.x; o[2][1] += p2*vv.y; o[2][2] += p2*vv.z; o[2][3] += p2*vv.w;
            o[3][0] += p3*vv.x; o[3][1] += p3*vv.y; o[3][2] += p3*vv.z; o[3][3] += p3*vv.w;
        }
    }

    const long outBase = (long)(b*SEQ + q0) * DIMD + h*DH;
    #pragma unroll
    for (int i = 0; i < 4; i++) {
        const float inv = 1.0f / l_run[i];
        float4 v = make_float4(o[i][0]*inv, o[i][1]*inv, o[i][2]*inv, o[i][3]*inv);
        *(float4*)(g_A + outBase + (long)(ty*4 + i)*DIMD + tx*4) = v;
    }
}

// ---------------------------------------------------------------------------
extern "C" void kernel_launch(void* const* d_in, const int* in_sizes, int n_in,
                              void* d_out, int out_size)
{
    const float* x      = (const float*)d_in[0];
    const float* w_qkv  = (const float*)d_in[1];
    const float* b_qkv  = (const float*)d_in[2];
    const float* w_proj = (const float*)d_in[3];
    const float* b_proj = (const float*)d_in[4];
    float* out = (float*)d_out;

    gemm_tf32<0><<<dim3(3*DIMD/128, MTOT/128), 256>>>(x, w_qkv, b_qkv, nullptr, 3*DIMD);
    attn_kernel<<<dim3(SEQ/64, NH, BATCH), 256>>>();
    gemm_tf32<1><<<dim3(DIMD/128, MTOT/128), 256>>>(nullptr, w_proj, b_proj, out, DIMD);
}

// round 3
// speedup vs baseline: 3.0772x; 1.9349x over previous
#include <cuda_runtime.h>

#define DIMD  1024
#define NH    16
#define DH    64
#define BATCH 4
#define SEQ   2048
#define MTOT  (BATCH*SEQ)   // 8192

// Scratch (allocation-free rule: __device__ globals)
__device__ float g_Q[BATCH*NH*SEQ*DH];   // [B,H,S,Dh]
__device__ float g_K[BATCH*NH*SEQ*DH];
__device__ float g_V[BATCH*NH*SEQ*DH];
__device__ float g_A[MTOT*DIMD];         // attention output, [B,S,D]

__device__ __forceinline__ float f2tf32(float x) {
    unsigned u;
    asm("cvt.rna.tf32.f32 %0, %1;" : "=r"(u) : "f"(x));
    return __uint_as_float(u);
}

__device__ __forceinline__ void mma_tf32(
    float& c0, float& c1, float& c2, float& c3,
    unsigned a0, unsigned a1, unsigned a2, unsigned a3,
    unsigned b0, unsigned b1)
{
    asm volatile(
        "mma.sync.aligned.m16n8k8.row.col.f32.tf32.tf32.f32 "
        "{%0,%1,%2,%3}, {%4,%5,%6,%7}, {%8,%9}, {%0,%1,%2,%3};"
        : "+f"(c0), "+f"(c1), "+f"(c2), "+f"(c3)
        : "r"(a0), "r"(a1), "r"(a2), "r"(a3), "r"(b0), "r"(b1));
}

// ---------------------------------------------------------------------------
// TF32 tensor-core GEMM (unchanged from round 2)
// ---------------------------------------------------------------------------
template<int MODE>
__global__ __launch_bounds__(256, 2)
void gemm_tf32(const float* __restrict__ A, const float* __restrict__ B,
               const float* __restrict__ bias, float* __restrict__ out, int N)
{
    const int K = DIMD;
    __shared__ float As[128][36];
    __shared__ float Bs[32][136];

    const int tid  = threadIdx.x;
    const int lane = tid & 31;
    const int warp = tid >> 5;
    const int warp_m = warp & 3;
    const int warp_n = warp >> 2;
    const int qr = lane >> 2;
    const int qc = lane & 3;

    const int rowStart = blockIdx.y * 128;
    const int colStart = blockIdx.x * 128;
    const float* Ap = (MODE == 0) ? A : g_A;

    float acc[2][8][4];
    #pragma unroll
    for (int i = 0; i < 2; i++)
        #pragma unroll
        for (int j = 0; j < 8; j++)
            #pragma unroll
            for (int c = 0; c < 4; c++) acc[i][j][c] = 0.f;

    for (int k0 = 0; k0 < K; k0 += 32) {
        float4 av[4], bv[4];
        #pragma unroll
        for (int i = 0; i < 4; i++) {
            const int q = tid + i*256;
            const int ar = q >> 3, akq = q & 7;
            av[i] = *(const float4*)(Ap + (long)(rowStart + ar)*K + k0 + akq*4);
            const int br = q >> 5, bnq = q & 31;
            bv[i] = *(const float4*)(B + (long)(k0 + br)*N + colStart + bnq*4);
        }
        __syncthreads();
        #pragma unroll
        for (int i = 0; i < 4; i++) {
            const int q = tid + i*256;
            const int ar = q >> 3, akq = q & 7;
            float* as = &As[ar][akq*4];
            as[0] = f2tf32(av[i].x); as[1] = f2tf32(av[i].y);
            as[2] = f2tf32(av[i].z); as[3] = f2tf32(av[i].w);
            const int br = q >> 5, bnq = q & 31;
            float* bs = &Bs[br][bnq*4];
            bs[0] = f2tf32(bv[i].x); bs[1] = f2tf32(bv[i].y);
            bs[2] = f2tf32(bv[i].z); bs[3] = f2tf32(bv[i].w);
        }
        __syncthreads();

        #pragma unroll
        for (int ks = 0; ks < 4; ks++) {
            const int kb = ks * 8;
            unsigned a[2][4], b[8][2];
            #pragma unroll
            for (int ma = 0; ma < 2; ma++) {
                const int r = warp_m*32 + ma*16 + qr;
                a[ma][0] = __float_as_uint(As[r    ][kb + qc    ]);
                a[ma][1] = __float_as_uint(As[r + 8][kb + qc    ]);
                a[ma][2] = __float_as_uint(As[r    ][kb + qc + 4]);
                a[ma][3] = __float_as_uint(As[r + 8][kb + qc + 4]);
            }
            #pragma unroll
            for (int nb = 0; nb < 8; nb++) {
                const int cc = warp_n*64 + nb*8 + qr;
                b[nb][0] = __float_as_uint(Bs[kb + qc    ][cc]);
                b[nb][1] = __float_as_uint(Bs[kb + qc + 4][cc]);
            }
            #pragma unroll
            for (int ma = 0; ma < 2; ma++)
                #pragma unroll
                for (int nb = 0; nb < 8; nb++)
                    mma_tf32(acc[ma][nb][0], acc[ma][nb][1],
                             acc[ma][nb][2], acc[ma][nb][3],
                             a[ma][0], a[ma][1], a[ma][2], a[ma][3],
                             b[nb][0], b[nb][1]);
        }
    }

    #pragma unroll
    for (int ma = 0; ma < 2; ma++) {
        const int row0 = rowStart + warp_m*32 + ma*16 + qr;
        #pragma unroll
        for (int nb = 0; nb < 8; nb++) {
            const int col = colStart + warp_n*64 + nb*8 + qc*2;
            const float b0 = bias[col], b1 = bias[col + 1];
            float2 v0 = make_float2(acc[ma][nb][0] + b0, acc[ma][nb][1] + b1);
            float2 v1 = make_float2(acc[ma][nb][2] + b0, acc[ma][nb][3] + b1);
            if (MODE == 0) {
                const int part = col >> 10;
                const int dcol = col & 1023;
                const int head = dcol >> 6;
                const int dh   = dcol & 63;
                float* dst = (part == 0) ? g_Q : (part == 1) ? g_K : g_V;
                {
                    const int bb = row0 >> 11, s = row0 & 2047;
                    *(float2*)(dst + (((bb*NH + head)*SEQ + s) << 6) + dh) = v0;
                }
                {
                    const int row1 = row0 + 8;
                    const int bb = row1 >> 11, s = row1 & 2047;
                    *(float2*)(dst + (((bb*NH + head)*SEQ + s) << 6) + dh) = v1;
                }
            } else {
                *(float2*)(out + (long)row0*N + col) = v0;
                *(float2*)(out + (long)(row0 + 8)*N + col) = v1;
            }
        }
    }
}

// ---------------------------------------------------------------------------
// TF32 tensor-core flash attention.
// Block = (b, h, 128-query tile), 256 threads = 8 warps, each warp owns 16
// full query rows. K-tiles of 64 keys. Q/K/P/V all tf32 via mma.m16n8k8.
// SMEM rows are 68 floats (68 % 32 == 4) -> conflict-free fragment LDS.
// ---------------------------------------------------------------------------
#define QS_OFF 0
#define KS_OFF 8704               // 128*68
#define VT_OFF 13056              // + 64*68
#define PS_OFF 17408              // + 64*68
#define ATTN_SMEM_FLOATS 26112    // + 128*68
#define ATTN_SMEM_BYTES (ATTN_SMEM_FLOATS*4)   // 104448

__global__ __launch_bounds__(256, 2)
void attn_tf32()
{
    extern __shared__ float sm[];
    float* Qs = sm + QS_OFF;   // [128][68]  tf32 Q (scaled)
    float* Ks = sm + KS_OFF;   // [64][68]   tf32 K, [key][d]
    float* Vt = sm + VT_OFF;   // [64][68]   tf32 V transposed, [d][key]
    float* Ps = sm + PS_OFF;   // [128][68]  tf32 P, [q][key]

    const int tid  = threadIdx.x;
    const int lane = tid & 31;
    const int warp = tid >> 5;          // 16-row strip
    const int qr = lane >> 2;           // 0..7
    const int qc = lane & 3;            // 0..3

    const int qt = (int)(gridDim.x - 1) - (int)blockIdx.x;   // heavy tiles first
    const int h = blockIdx.y, b = blockIdx.z;
    const int q0 = qt << 7;

    const long hb = (long)(b*NH + h) * SEQ * DH;
    const float* Qg = g_Q + hb;
    const float* Kg = g_K + hb;
    const float* Vg = g_V + hb;

    // Load Q tile [128][64], scale by 1/8, convert tf32
    #pragma unroll
    for (int i = 0; i < 8; i++) {
        const int q = tid + i*256;           // quad id (2048 quads)
        const int r = q >> 4, dq = (q & 15) << 2;
        float4 t = *(const float4*)(Qg + (q0 + r)*DH + dq);
        float4 c;
        c.x = f2tf32(t.x * 0.125f); c.y = f2tf32(t.y * 0.125f);
        c.z = f2tf32(t.z * 0.125f); c.w = f2tf32(t.w * 0.125f);
        *(float4*)(Qs + r*68 + dq) = c;
    }

    float m0 = -1e30f, m1 = -1e30f, l0 = 0.f, l1 = 0.f;
    float o[8][4];
    #pragma unroll
    for (int nb = 0; nb < 8; nb++)
        #pragma unroll
        for (int c = 0; c < 4; c++) o[nb][c] = 0.f;

    const int rowA = warp*16 + qr;       // local q row (and +8)
    const int ktiles = 2*qt + 2;

    for (int kt = 0; kt < ktiles; kt++) {
        const int k0 = kt << 6;
        __syncthreads();   // prior PV reads of Vt/Ps done; Q visible (iter 0)

        // K tile -> Ks[key][d] (tf32)
        #pragma unroll
        for (int i = 0; i < 4; i++) {
            const int q = tid + i*256;        // 1024 quads
            const int r = q >> 4, dq = (q & 15) << 2;
            float4 t = *(const float4*)(Kg + (k0 + r)*DH + dq);
            float4 c;
            c.x = f2tf32(t.x); c.y = f2tf32(t.y);
            c.z = f2tf32(t.z); c.w = f2tf32(t.w);
            *(float4*)(Ks + r*68 + dq) = c;
        }
        // V tile -> Vt[d][key] transposed (tf32); key-contiguous lanes keep stores conflict-free
        {
            const int key = tid & 63;
            const int dq0 = (tid >> 6) << 2;
            #pragma unroll
            for (int i = 0; i < 4; i++) {
                const int dq = dq0 + i*16;
                float4 t = *(const float4*)(Vg + (k0 + key)*DH + dq);
                Vt[(dq+0)*68 + key] = f2tf32(t.x);
                Vt[(dq+1)*68 + key] = f2tf32(t.y);
                Vt[(dq+2)*68 + key] = f2tf32(t.z);
                Vt[(dq+3)*68 + key] = f2tf32(t.w);
            }
        }
        __syncthreads();

        // S = Q @ K^T : warp rows [warp*16, +16), keys [0,64)
        float sv[8][4];
        #pragma unroll
        for (int nb = 0; nb < 8; nb++)
            #pragma unroll
            for (int c = 0; c < 4; c++) sv[nb][c] = 0.f;

        #pragma unroll
        for (int ks = 0; ks < 8; ks++) {
            const int kb = ks*8;
            const unsigned a0 = __float_as_uint(Qs[(rowA    )*68 + kb+qc  ]);
            const unsigned a1 = __float_as_uint(Qs[(rowA + 8)*68 + kb+qc  ]);
            const unsigned a2 = __float_as_uint(Qs[(rowA    )*68 + kb+qc+4]);
            const unsigned a3 = __float_as_uint(Qs[(rowA + 8)*68 + kb+qc+4]);
            #pragma unroll
            for (int nb = 0; nb < 8; nb++) {
                const unsigned b0 = __float_as_uint(Ks[(nb*8+qr)*68 + kb+qc  ]);
                const unsigned b1 = __float_as_uint(Ks[(nb*8+qr)*68 + kb+qc+4]);
                mma_tf32(sv[nb][0], sv[nb][1], sv[nb][2], sv[nb][3],
                         a0, a1, a2, a3, b0, b1);
            }
        }

        // Causal mask (only the two diagonal k-tiles need it)
        if (kt >= 2*qt) {
            const int qg0 = q0 + rowA;
            #pragma unroll
            for (int nb = 0; nb < 8; nb++) {
                const int kg = k0 + nb*8 + 2*qc;
                if (kg     > qg0    ) sv[nb][0] = -1e30f;
                if (kg + 1 > qg0    ) sv[nb][1] = -1e30f;
                if (kg     > qg0 + 8) sv[nb][2] = -1e30f;
                if (kg + 1 > qg0 + 8) sv[nb][3] = -1e30f;
            }
        }

        // Online softmax (rows qr and qr+8; stats across the 4 qc lanes)
        float mx0 = -1e30f, mx1 = -1e30f;
        #pragma unroll
        for (int nb = 0; nb < 8; nb++) {
            mx0 = fmaxf(mx0, fmaxf(sv[nb][0], sv[nb][1]));
            mx1 = fmaxf(mx1, fmaxf(sv[nb][2], sv[nb][3]));
        }
        mx0 = fmaxf(mx0, __shfl_xor_sync(0xffffffffu, mx0, 1));
        mx0 = fmaxf(mx0, __shfl_xor_sync(0xffffffffu, mx0, 2));
        mx1 = fmaxf(mx1, __shfl_xor_sync(0xffffffffu, mx1, 1));
        mx1 = fmaxf(mx1, __shfl_xor_sync(0xffffffffu, mx1, 2));

        const float m0n = fmaxf(m0, mx0);
        const float m1n = fmaxf(m1, mx1);
        const float al0 = __expf(m0 - m0n);
        const float al1 = __expf(m1 - m1n);
        m0 = m0n; m1 = m1n;

        float ps0 = 0.f, ps1 = 0.f;
        #pragma unroll
        for (int nb = 0; nb < 8; nb++) {
            sv[nb][0] = __expf(sv[nb][0] - m0n);
            sv[nb][1] = __expf(sv[nb][1] - m0n);
            sv[nb][2] = __expf(sv[nb][2] - m1n);
            sv[nb][3] = __expf(sv[nb][3] - m1n);
            ps0 += sv[nb][0] + sv[nb][1];
            ps1 += sv[nb][2] + sv[nb][3];
        }
        ps0 += __shfl_xor_sync(0xffffffffu, ps0, 1);
        ps0 += __shfl_xor_sync(0xffffffffu, ps0, 2);
        ps1 += __shfl_xor_sync(0xffffffffu, ps1, 1);
        ps1 += __shfl_xor_sync(0xffffffffu, ps1, 2);
        l0 = l0*al0 + ps0;
        l1 = l1*al1 + ps1;
        #pragma unroll
        for (int nb = 0; nb < 8; nb++) {
            o[nb][0] *= al0; o[nb][1] *= al0;
            o[nb][2] *= al1; o[nb][3] *= al1;
        }

        // Store P (tf32) to SMEM: Ps[q][key]
        #pragma unroll
        for (int nb = 0; nb < 8; nb++) {
            const int kc = nb*8 + 2*qc;
            *(float2*)(Ps + (rowA    )*68 + kc) =
                make_float2(f2tf32(sv[nb][0]), f2tf32(sv[nb][1]));
            *(float2*)(Ps + (rowA + 8)*68 + kc) =
                make_float2(f2tf32(sv[nb][2]), f2tf32(sv[nb][3]));
        }
        __syncthreads();

        // O += P @ V   (n = d in [0,64), k = key in [0,64))
        #pragma unroll
        for (int ks = 0; ks < 8; ks++) {
            const int kb = ks*8;
            const unsigned a0 = __float_as_uint(Ps[(rowA    )*68 + kb+qc  ]);
            const unsigned a1 = __float_as_uint(Ps[(rowA + 8)*68 + kb+qc  ]);
            const unsigned a2 = __float_as_uint(Ps[(rowA    )*68 + kb+qc+4]);
            const unsigned a3 = __float_as_uint(Ps[(rowA + 8)*68 + kb+qc+4]);
            #pragma unroll
            for (int nb = 0; nb < 8; nb++) {
                const unsigned b0 = __float_as_uint(Vt[(nb*8+qr)*68 + kb+qc  ]);
                const unsigned b1 = __float_as_uint(Vt[(nb*8+qr)*68 + kb+qc+4]);
                mma_tf32(o[nb][0], o[nb][1], o[nb][2], o[nb][3],
                         a0, a1, a2, a3, b0, b1);
            }
        }
    }

    // Normalize, write merged-head layout [B,S,D]
    const float inv0 = 1.0f / l0;
    const float inv1 = 1.0f / l1;
    const long r0 = (long)(b*SEQ + q0 + rowA);
    #pragma unroll
    for (int nb = 0; nb < 8; nb++) {
        const int col = h*DH + nb*8 + 2*qc;
        *(float2*)(g_A + r0*DIMD + col) =
            make_float2(o[nb][0]*inv0, o[nb][1]*inv0);
        *(float2*)(g_A + (r0 + 8)*DIMD + col) =
            make_float2(o[nb][2]*inv1, o[nb][3]*inv1);
    }
}

// ---------------------------------------------------------------------------
extern "C" void kernel_launch(void* const* d_in, const int* in_sizes, int n_in,
                              void* d_out, int out_size)
{
    const float* x      = (const float*)d_in[0];
    const float* w_qkv  = (const float*)d_in[1];
    const float* b_qkv  = (const float*)d_in[2];
    const float* w_proj = (const float*)d_in[3];
    const float* b_proj = (const float*)d_in[4];
    float* out = (float*)d_out;

    cudaFuncSetAttribute(attn_tf32,
        cudaFuncAttributeMaxDynamicSharedMemorySize, ATTN_SMEM_BYTES);

    gemm_tf32<0><<<dim3(3*DIMD/128, MTOT/128), 256>>>(x, w_qkv, b_qkv, nullptr, 3*DIMD);
    attn_tf32<<<dim3(SEQ/128, NH, BATCH), 256, ATTN_SMEM_BYTES>>>();
    gemm_tf32<1><<<dim3(DIMD/128, MTOT/128), 256>>>(nullptr, w_proj, b_proj, out, DIMD);
}